// round 7
// baseline (speedup 1.0000x reference)
#include <cuda_runtime.h>

// ---------------------------------------------------------------------------
// Quanvolution filter, algebraically collapsed:
//   <Z_w>(patch) = sum_{t in {I,C,S}^4} coef[w][t] * prod_i f_{t_i}(x_i)
// f_I = 1, f_C = cos(x_i), f_S = sin(x_i).  coef depends only on params.
//
// Main kernel: one thread = one PATCH-PAIR (two horizontally adjacent
// patches) packed into the two lanes of f32x2 registers. Per-wire
// accumulator chains (4 independent FFMA2 chains), coefficients duplicated
// (c,c) in shared memory so they can be FFMA2 operands directly.
// ---------------------------------------------------------------------------

typedef unsigned long long ull;

// duplicated coefs: g_dup[q*4 + w] = (coef, coef), q = ((t0*3+t1)*3+t2)*3+t3
__device__ __align__(16) ull g_dup[324];

// ---------------------------------------------------------------------------
// Setup: one block, 256 threads.
// ---------------------------------------------------------------------------
__global__ void quanv_setup_kernel(const float* __restrict__ params)
{
    __shared__ float  Gr[8][4];
    __shared__ float  Gi[8][4];
    __shared__ float2 cs[256];     // [j*16 + m]
    __shared__ float  Wr[16][16];  // W[m][j]
    __shared__ float  Wi[16][16];
    __shared__ float  A[4][16][16];

    const int tid = threadIdx.x;

    if (tid < 8) {
        const float a = params[tid * 3 + 0] * 0.5f;
        const float b = params[tid * 3 + 1] * 0.5f;
        const float c = params[tid * 3 + 2] * 0.5f;
        const float ca = cosf(a), sa = sinf(a);
        const float cb = cosf(b), sb = sinf(b);
        const float cc = cosf(c), sc = sinf(c);
        const float m00r =  cb * ca, m00i = -sb * ca;
        const float m01r = -cb * sa, m01i =  sb * sa;
        const float m10r =  cb * sa, m10i =  sb * sa;
        const float m11r =  cb * ca, m11i =  sb * ca;
        Gr[tid][0] = cc * m00r + sc * m10i;  Gi[tid][0] = cc * m00i - sc * m10r;
        Gr[tid][1] = cc * m01r + sc * m11i;  Gi[tid][1] = cc * m01i - sc * m11r;
        Gr[tid][2] = cc * m10r + sc * m00i;  Gi[tid][2] = cc * m10i - sc * m00r;
        Gr[tid][3] = cc * m11r + sc * m01i;  Gi[tid][3] = cc * m11i - sc * m01r;
    }
    __syncthreads();

    const int j = tid >> 4;
    const int m = tid & 15;
    float2 s = (m == j) ? make_float2(1.f, 0.f) : make_float2(0.f, 0.f);

    #pragma unroll
    for (int l = 0; l < 2; l++) {
        #pragma unroll
        for (int w = 0; w < 4; w++) {
            cs[tid] = s;
            __syncthreads();
            const int mask = 8 >> w;
            const int bsel = (m & mask) ? 1 : 0;
            const float2 s0 = cs[(j << 4) | (m & ~mask)];
            const float2 s1 = cs[(j << 4) | (m |  mask)];
            const int g = l * 4 + w;
            const float g0r = Gr[g][bsel * 2 + 0], g0i = Gi[g][bsel * 2 + 0];
            const float g1r = Gr[g][bsel * 2 + 1], g1i = Gi[g][bsel * 2 + 1];
            float2 ns;
            ns.x = g0r * s0.x - g0i * s0.y + g1r * s1.x - g1i * s1.y;
            ns.y = g0r * s0.y + g0i * s0.x + g1r * s1.y + g1i * s1.x;
            s = ns;
            __syncthreads();
        }
        cs[tid] = s;
        __syncthreads();
        int ms = m;
        ms ^= (ms & 1) ? 8 : 0;
        ms ^= (ms & 2) ? 1 : 0;
        ms ^= (ms & 4) ? 2 : 0;
        ms ^= (ms & 8) ? 4 : 0;
        s = cs[(j << 4) | ms];
        __syncthreads();
    }
    Wr[m][j] = s.x;
    Wi[m][j] = s.y;
    __syncthreads();

    {
        const int jj = tid >> 4, kk = tid & 15;
        float acc0 = 0.f, acc1 = 0.f, acc2 = 0.f, acc3 = 0.f;
        #pragma unroll
        for (int mm = 0; mm < 16; mm++) {
            const float v = Wr[mm][jj] * Wr[mm][kk] + Wi[mm][jj] * Wi[mm][kk];
            acc0 += ((mm >> 3) & 1) ? -v : v;
            acc1 += ((mm >> 2) & 1) ? -v : v;
            acc2 += ((mm >> 1) & 1) ? -v : v;
            acc3 += ( mm       & 1) ? -v : v;
        }
        A[0][jj][kk] = acc0; A[1][jj][kk] = acc1;
        A[2][jj][kk] = acc2; A[3][jj][kk] = acc3;
    }
    __syncthreads();

    for (int idx = tid; idx < 324; idx += 256) {
        const int q = idx >> 2, w = idx & 3;
        const int t0 = q / 27, t1 = (q / 9) % 3, t2 = (q / 3) % 3, t3 = q % 3;
        int smask = 0, cmask = 0;
        if (t0 == 2) smask |= 8; else if (t0 == 1) cmask |= 8;
        if (t1 == 2) smask |= 4; else if (t1 == 1) cmask |= 4;
        if (t2 == 2) smask |= 2; else if (t2 == 1) cmask |= 2;
        if (t3 == 2) smask |= 1; else if (t3 == 1) cmask |= 1;
        float c = 0.f;
        #pragma unroll
        for (int u = 0; u < 16; u++) {
            const float v = A[w][u][u ^ smask];
            c += (__popc(u & cmask) & 1) ? -v : v;
        }
        c *= 0.0625f;
        ull d;
        asm("mov.b64 %0, {%1, %1};" : "=l"(d) : "f"(c));
        g_dup[idx] = d;
    }
}

// ---------------------------------------------------------------------------
// Packed f32x2 helpers (Blackwell sm_100+).
// ---------------------------------------------------------------------------
__device__ __forceinline__ ull ffma2(ull a, ull b, ull c) {
    ull d;
    asm("fma.rn.f32x2 %0, %1, %2, %3;" : "=l"(d) : "l"(a), "l"(b), "l"(c));
    return d;
}
__device__ __forceinline__ ull pack2f(float x, float y) {
    ull d;
    asm("mov.b64 %0, {%1, %2};" : "=l"(d) : "f"(x), "f"(y));
    return d;
}
__device__ __forceinline__ void unpack2(ull v, float& lo, float& hi) {
    asm("mov.b64 {%0, %1}, %2;" : "=f"(lo), "=f"(hi) : "l"(v));
}

// ---------------------------------------------------------------------------
// Main kernel: 128 threads/block, 1 patch-pair/thread (2 patches).
// Pair pp -> image b = pp/98, row r = (pp%98)/7, col-pair cp = (pp%98)%7.
// Patch A = (top.x,top.y,bot.x,bot.y), patch B = (top.z,top.w,bot.z,bot.w).
// f32x2 lanes = (A, B). 4 per-wire accumulator chains.
// ---------------------------------------------------------------------------
__global__ void __launch_bounds__(128, 6)
quanv_main_kernel(const float* __restrict__ x, float* __restrict__ out)
{
    __shared__ __align__(16) ull sh[324];
    const int tid = threadIdx.x;

    // 162 ulonglong2 total; 128 threads -> strided (THE R6 BUG: was `if (tid<162)`)
    #pragma unroll
    for (int i = tid; i < 162; i += 128)
        ((ulonglong2*)sh)[i] = ((const ulonglong2*)g_dup)[i];
    __syncthreads();

    const int pp  = blockIdx.x * 128 + tid;        // pair index [0, 401408)
    const int b   = pp / 98;
    const int rem = pp - b * 98;
    const int r   = rem / 7;
    const int cp  = rem - r * 7;

    const float* xp = x + b * 784 + r * 56 + cp * 4;
    const float4 top = *(const float4*)xp;
    const float4 bot = *(const float4*)(xp + 28);

    float sA, cA, sB, cB;
    __sincosf(top.x, &sA, &cA); __sincosf(top.z, &sB, &cB);
    const ull c0 = pack2f(cA, cB), s0 = pack2f(sA, sB);
    __sincosf(top.y, &sA, &cA); __sincosf(top.w, &sB, &cB);
    const ull c1 = pack2f(cA, cB), s1 = pack2f(sA, sB);
    __sincosf(bot.x, &sA, &cA); __sincosf(bot.z, &sB, &cB);
    const ull c2 = pack2f(cA, cB), s2 = pack2f(sA, sB);
    __sincosf(bot.y, &sA, &cA); __sincosf(bot.w, &sB, &cB);
    const ull c3 = pack2f(cA, cB), s3 = pack2f(sA, sB);

    ull a0[4], a1[4], a2[4];

    #pragma unroll
    for (int t0 = 0; t0 < 3; t0++) {
        #pragma unroll
        for (int t1 = 0; t1 < 3; t1++) {
            #pragma unroll
            for (int t2 = 0; t2 < 3; t2++) {
                const int qb = ((t0 * 3 + t1) * 3 + t2) * 3;  // q at t3=0
                const ulonglong2 L0 = ((const ulonglong2*)sh)[qb * 2 + 0];
                const ulonglong2 L1 = ((const ulonglong2*)sh)[qb * 2 + 1];
                const ulonglong2 L2 = ((const ulonglong2*)sh)[qb * 2 + 2];
                const ulonglong2 L3 = ((const ulonglong2*)sh)[qb * 2 + 3];
                const ulonglong2 L4 = ((const ulonglong2*)sh)[qb * 2 + 4];
                const ulonglong2 L5 = ((const ulonglong2*)sh)[qb * 2 + 5];

                const ull i0 = ffma2(L4.x, s3, ffma2(L2.x, c3, L0.x));
                const ull i1 = ffma2(L4.y, s3, ffma2(L2.y, c3, L0.y));
                const ull i2 = ffma2(L5.x, s3, ffma2(L3.x, c3, L1.x));
                const ull i3 = ffma2(L5.y, s3, ffma2(L3.y, c3, L1.y));

                if (t2 == 0) {
                    a2[0] = i0; a2[1] = i1; a2[2] = i2; a2[3] = i3;
                } else {
                    const ull f = (t2 == 1) ? c2 : s2;
                    a2[0] = ffma2(i0, f, a2[0]);
                    a2[1] = ffma2(i1, f, a2[1]);
                    a2[2] = ffma2(i2, f, a2[2]);
                    a2[3] = ffma2(i3, f, a2[3]);
                }
            }
            if (t1 == 0) {
                a1[0] = a2[0]; a1[1] = a2[1]; a1[2] = a2[2]; a1[3] = a2[3];
            } else {
                const ull f = (t1 == 1) ? c1 : s1;
                a1[0] = ffma2(a2[0], f, a1[0]);
                a1[1] = ffma2(a2[1], f, a1[1]);
                a1[2] = ffma2(a2[2], f, a1[2]);
                a1[3] = ffma2(a2[3], f, a1[3]);
            }
        }
        if (t0 == 0) {
            a0[0] = a1[0]; a0[1] = a1[1]; a0[2] = a1[2]; a0[3] = a1[3];
        } else {
            const ull f = (t0 == 1) ? c0 : s0;
            a0[0] = ffma2(a1[0], f, a0[0]);
            a0[1] = ffma2(a1[1], f, a0[1]);
            a0[2] = ffma2(a1[2], f, a0[2]);
            a0[3] = ffma2(a1[3], f, a0[3]);
        }
    }

    float4 oA, oB;
    unpack2(a0[0], oA.x, oB.x);
    unpack2(a0[1], oA.y, oB.y);
    unpack2(a0[2], oA.z, oB.z);
    unpack2(a0[3], oA.w, oB.w);
    ((float4*)out)[2 * pp]     = oA;
    ((float4*)out)[2 * pp + 1] = oB;
}

extern "C" void kernel_launch(void* const* d_in, const int* in_sizes, int n_in,
                              void* d_out, int out_size)
{
    const float* x      = (const float*)d_in[0];
    const float* params = (const float*)d_in[1];
    if (n_in >= 2 && in_sizes[0] == 24) {
        params = (const float*)d_in[0];
        x      = (const float*)d_in[1];
    }
    float* out = (float*)d_out;

    quanv_setup_kernel<<<1, 256>>>(params);
    // 401408 pairs / 128 threads = 3136 blocks exactly
    quanv_main_kernel<<<3136, 128>>>(x, out);
}

// round 8
// speedup vs baseline: 1.1810x; 1.1810x over previous
#include <cuda_runtime.h>

// ---------------------------------------------------------------------------
// Quanvolution filter, algebraically collapsed:
//   <Z_w>(patch) = sum_{t in {I,C,S}^4} coef[w][t] * prod_i f_{t_i}(x_i)
// f_I = 1, f_C = cos(x_i), f_S = sin(x_i).  coef depends only on params.
//
// Main kernel: one thread = TWO patch-pairs (4 patches). Each pair's two
// horizontally adjacent patches ride the two lanes of f32x2 registers
// (Blackwell FFMA2). Coefficients are duplicated (c,c) in shared memory and
// each broadcast LDS.128 is reused by both pairs -> 40.5 LDS.128/patch.
// ---------------------------------------------------------------------------

typedef unsigned long long ull;

// duplicated coefs: g_dup[q*4 + w] = (coef, coef), q = ((t0*3+t1)*3+t2)*3+t3
__device__ __align__(16) ull g_dup[324];

// ---------------------------------------------------------------------------
// Setup: one block, 256 threads.
// ---------------------------------------------------------------------------
__global__ void quanv_setup_kernel(const float* __restrict__ params)
{
    __shared__ float  Gr[8][4];
    __shared__ float  Gi[8][4];
    __shared__ float2 cs[256];     // [j*16 + m]
    __shared__ float  Wr[16][16];  // W[m][j]
    __shared__ float  Wi[16][16];
    __shared__ float  A[4][16][16];

    const int tid = threadIdx.x;

    if (tid < 8) {
        const float a = params[tid * 3 + 0] * 0.5f;
        const float b = params[tid * 3 + 1] * 0.5f;
        const float c = params[tid * 3 + 2] * 0.5f;
        const float ca = cosf(a), sa = sinf(a);
        const float cb = cosf(b), sb = sinf(b);
        const float cc = cosf(c), sc = sinf(c);
        const float m00r =  cb * ca, m00i = -sb * ca;
        const float m01r = -cb * sa, m01i =  sb * sa;
        const float m10r =  cb * sa, m10i =  sb * sa;
        const float m11r =  cb * ca, m11i =  sb * ca;
        Gr[tid][0] = cc * m00r + sc * m10i;  Gi[tid][0] = cc * m00i - sc * m10r;
        Gr[tid][1] = cc * m01r + sc * m11i;  Gi[tid][1] = cc * m01i - sc * m11r;
        Gr[tid][2] = cc * m10r + sc * m00i;  Gi[tid][2] = cc * m10i - sc * m00r;
        Gr[tid][3] = cc * m11r + sc * m01i;  Gi[tid][3] = cc * m11i - sc * m01r;
    }
    __syncthreads();

    const int j = tid >> 4;
    const int m = tid & 15;
    float2 s = (m == j) ? make_float2(1.f, 0.f) : make_float2(0.f, 0.f);

    #pragma unroll
    for (int l = 0; l < 2; l++) {
        #pragma unroll
        for (int w = 0; w < 4; w++) {
            cs[tid] = s;
            __syncthreads();
            const int mask = 8 >> w;
            const int bsel = (m & mask) ? 1 : 0;
            const float2 s0 = cs[(j << 4) | (m & ~mask)];
            const float2 s1 = cs[(j << 4) | (m |  mask)];
            const int g = l * 4 + w;
            const float g0r = Gr[g][bsel * 2 + 0], g0i = Gi[g][bsel * 2 + 0];
            const float g1r = Gr[g][bsel * 2 + 1], g1i = Gi[g][bsel * 2 + 1];
            float2 ns;
            ns.x = g0r * s0.x - g0i * s0.y + g1r * s1.x - g1i * s1.y;
            ns.y = g0r * s0.y + g0i * s0.x + g1r * s1.y + g1i * s1.x;
            s = ns;
            __syncthreads();
        }
        cs[tid] = s;
        __syncthreads();
        int ms = m;
        ms ^= (ms & 1) ? 8 : 0;
        ms ^= (ms & 2) ? 1 : 0;
        ms ^= (ms & 4) ? 2 : 0;
        ms ^= (ms & 8) ? 4 : 0;
        s = cs[(j << 4) | ms];
        __syncthreads();
    }
    Wr[m][j] = s.x;
    Wi[m][j] = s.y;
    __syncthreads();

    {
        const int jj = tid >> 4, kk = tid & 15;
        float acc0 = 0.f, acc1 = 0.f, acc2 = 0.f, acc3 = 0.f;
        #pragma unroll
        for (int mm = 0; mm < 16; mm++) {
            const float v = Wr[mm][jj] * Wr[mm][kk] + Wi[mm][jj] * Wi[mm][kk];
            acc0 += ((mm >> 3) & 1) ? -v : v;
            acc1 += ((mm >> 2) & 1) ? -v : v;
            acc2 += ((mm >> 1) & 1) ? -v : v;
            acc3 += ( mm       & 1) ? -v : v;
        }
        A[0][jj][kk] = acc0; A[1][jj][kk] = acc1;
        A[2][jj][kk] = acc2; A[3][jj][kk] = acc3;
    }
    __syncthreads();

    for (int idx = tid; idx < 324; idx += 256) {
        const int q = idx >> 2, w = idx & 3;
        const int t0 = q / 27, t1 = (q / 9) % 3, t2 = (q / 3) % 3, t3 = q % 3;
        int smask = 0, cmask = 0;
        if (t0 == 2) smask |= 8; else if (t0 == 1) cmask |= 8;
        if (t1 == 2) smask |= 4; else if (t1 == 1) cmask |= 4;
        if (t2 == 2) smask |= 2; else if (t2 == 1) cmask |= 2;
        if (t3 == 2) smask |= 1; else if (t3 == 1) cmask |= 1;
        float c = 0.f;
        #pragma unroll
        for (int u = 0; u < 16; u++) {
            const float v = A[w][u][u ^ smask];
            c += (__popc(u & cmask) & 1) ? -v : v;
        }
        c *= 0.0625f;
        ull d;
        asm("mov.b64 %0, {%1, %1};" : "=l"(d) : "f"(c));
        g_dup[idx] = d;
    }
}

// ---------------------------------------------------------------------------
// Packed f32x2 helpers (Blackwell sm_100+).
// ---------------------------------------------------------------------------
__device__ __forceinline__ ull ffma2(ull a, ull b, ull c) {
    ull d;
    asm("fma.rn.f32x2 %0, %1, %2, %3;" : "=l"(d) : "l"(a), "l"(b), "l"(c));
    return d;
}
__device__ __forceinline__ ull pack2f(float x, float y) {
    ull d;
    asm("mov.b64 %0, {%1, %2};" : "=l"(d) : "f"(x), "f"(y));
    return d;
}
__device__ __forceinline__ void unpack2(ull v, float& lo, float& hi) {
    asm("mov.b64 {%0, %1}, %2;" : "=f"(lo), "=f"(hi) : "l"(v));
}

struct PairTrig { ull c0, s0, c1, s1, c2, s2, c3, s3; };

__device__ __forceinline__ PairTrig load_pair_trig(const float* __restrict__ x, int pp)
{
    const int b   = pp / 98;
    const int rem = pp - b * 98;
    const int r   = rem / 7;
    const int cp  = rem - r * 7;

    const float* xp = x + b * 784 + r * 56 + cp * 4;
    const float4 top = *(const float4*)xp;
    const float4 bot = *(const float4*)(xp + 28);

    PairTrig t;
    float sA, cA, sB, cB;
    __sincosf(top.x, &sA, &cA); __sincosf(top.z, &sB, &cB);
    t.c0 = pack2f(cA, cB); t.s0 = pack2f(sA, sB);
    __sincosf(top.y, &sA, &cA); __sincosf(top.w, &sB, &cB);
    t.c1 = pack2f(cA, cB); t.s1 = pack2f(sA, sB);
    __sincosf(bot.x, &sA, &cA); __sincosf(bot.z, &sB, &cB);
    t.c2 = pack2f(cA, cB); t.s2 = pack2f(sA, sB);
    __sincosf(bot.y, &sA, &cA); __sincosf(bot.w, &sB, &cB);
    t.c3 = pack2f(cA, cB); t.s3 = pack2f(sA, sB);
    return t;
}

// ---------------------------------------------------------------------------
// Main kernel: 128 threads/block, 2 patch-pairs/thread (4 patches).
// Coefficient LDS.128 loads shared by both pairs.
// ---------------------------------------------------------------------------
#define NP 2   // pairs per thread

__global__ void __launch_bounds__(128, 4)
quanv_main_kernel(const float* __restrict__ x, float* __restrict__ out)
{
    __shared__ __align__(16) ull sh[324];
    const int tid = threadIdx.x;

    #pragma unroll
    for (int i = tid; i < 162; i += 128)
        ((ulonglong2*)sh)[i] = ((const ulonglong2*)g_dup)[i];
    __syncthreads();

    const int base = blockIdx.x * (128 * NP) + tid;

    PairTrig tg[NP];
    #pragma unroll
    for (int p = 0; p < NP; p++) tg[p] = load_pair_trig(x, base + p * 128);

    ull a0[NP][4], a1[NP][4], a2[NP][4];

    #pragma unroll
    for (int t0 = 0; t0 < 3; t0++) {
        #pragma unroll
        for (int t1 = 0; t1 < 3; t1++) {
            #pragma unroll
            for (int t2 = 0; t2 < 3; t2++) {
                const int qb = ((t0 * 3 + t1) * 3 + t2) * 3;  // q at t3=0
                const ulonglong2 L0 = ((const ulonglong2*)sh)[qb * 2 + 0];
                const ulonglong2 L1 = ((const ulonglong2*)sh)[qb * 2 + 1];
                const ulonglong2 L2 = ((const ulonglong2*)sh)[qb * 2 + 2];
                const ulonglong2 L3 = ((const ulonglong2*)sh)[qb * 2 + 3];
                const ulonglong2 L4 = ((const ulonglong2*)sh)[qb * 2 + 4];
                const ulonglong2 L5 = ((const ulonglong2*)sh)[qb * 2 + 5];

                #pragma unroll
                for (int p = 0; p < NP; p++) {
                    const ull i0 = ffma2(L4.x, tg[p].s3, ffma2(L2.x, tg[p].c3, L0.x));
                    const ull i1 = ffma2(L4.y, tg[p].s3, ffma2(L2.y, tg[p].c3, L0.y));
                    const ull i2 = ffma2(L5.x, tg[p].s3, ffma2(L3.x, tg[p].c3, L1.x));
                    const ull i3 = ffma2(L5.y, tg[p].s3, ffma2(L3.y, tg[p].c3, L1.y));

                    if (t2 == 0) {
                        a2[p][0] = i0; a2[p][1] = i1; a2[p][2] = i2; a2[p][3] = i3;
                    } else {
                        const ull f = (t2 == 1) ? tg[p].c2 : tg[p].s2;
                        a2[p][0] = ffma2(i0, f, a2[p][0]);
                        a2[p][1] = ffma2(i1, f, a2[p][1]);
                        a2[p][2] = ffma2(i2, f, a2[p][2]);
                        a2[p][3] = ffma2(i3, f, a2[p][3]);
                    }
                }
            }
            #pragma unroll
            for (int p = 0; p < NP; p++) {
                if (t1 == 0) {
                    a1[p][0] = a2[p][0]; a1[p][1] = a2[p][1];
                    a1[p][2] = a2[p][2]; a1[p][3] = a2[p][3];
                } else {
                    const ull f = (t1 == 1) ? tg[p].c1 : tg[p].s1;
                    a1[p][0] = ffma2(a2[p][0], f, a1[p][0]);
                    a1[p][1] = ffma2(a2[p][1], f, a1[p][1]);
                    a1[p][2] = ffma2(a2[p][2], f, a1[p][2]);
                    a1[p][3] = ffma2(a2[p][3], f, a1[p][3]);
                }
            }
        }
        #pragma unroll
        for (int p = 0; p < NP; p++) {
            if (t0 == 0) {
                a0[p][0] = a1[p][0]; a0[p][1] = a1[p][1];
                a0[p][2] = a1[p][2]; a0[p][3] = a1[p][3];
            } else {
                const ull f = (t0 == 1) ? tg[p].c0 : tg[p].s0;
                a0[p][0] = ffma2(a1[p][0], f, a0[p][0]);
                a0[p][1] = ffma2(a1[p][1], f, a0[p][1]);
                a0[p][2] = ffma2(a1[p][2], f, a0[p][2]);
                a0[p][3] = ffma2(a1[p][3], f, a0[p][3]);
            }
        }
    }

    #pragma unroll
    for (int p = 0; p < NP; p++) {
        const int pp = base + p * 128;
        float4 oA, oB;
        unpack2(a0[p][0], oA.x, oB.x);
        unpack2(a0[p][1], oA.y, oB.y);
        unpack2(a0[p][2], oA.z, oB.z);
        unpack2(a0[p][3], oA.w, oB.w);
        ((float4*)out)[2 * pp]     = oA;
        ((float4*)out)[2 * pp + 1] = oB;
    }
}

extern "C" void kernel_launch(void* const* d_in, const int* in_sizes, int n_in,
                              void* d_out, int out_size)
{
    const float* x      = (const float*)d_in[0];
    const float* params = (const float*)d_in[1];
    if (n_in >= 2 && in_sizes[0] == 24) {
        params = (const float*)d_in[0];
        x      = (const float*)d_in[1];
    }
    float* out = (float*)d_out;

    quanv_setup_kernel<<<1, 256>>>(params);
    // 401408 pairs / (128 threads * 2 pairs) = 1568 blocks exactly
    quanv_main_kernel<<<1568, 128>>>(x, out);
}